// round 13
// baseline (speedup 1.0000x reference)
#include <cuda_runtime.h>
#include <cuda_fp16.h>
#include <cstdint>

// ---------------------------------------------------------------------------
// out[512, 65536] = inputs[512,256] @ features[65536,256]^T   (fp32 in/out)
//
// Toolchain: compute_103 virtual arch -> no tcgen05; tensor path is
// ldmatrix + mma.sync.m16n8k16.
//
// R13 RATE PROBE: the 59us mainloop floor is set by the f32-accumulate
// HMMA. This round switches the inner chain to the f16-accumulate variant
// (mma.sync...f16.f16.f16.f16), which on consumer Blackwell runs 2x faster.
// Accumulation: chains of 2 MMAs (K=32) in fp16, folded into f32 registers
// (error budget ~5.6e-4 < 1e-3). If sm_103a runs f16-accum at 2x -> gemm
// ~35us; if equal-rate -> neutral and we revert.
//
// Structure (R6, best mainloop family): convert kernel fp32->fp16 globals;
// gemm 148 CTAs x 256 threads, CTA tile M=128 x N=128 x K=256, B tiles
// double-buffered via cp.async (prefetch dist 2), warp tile 64x32.
// ---------------------------------------------------------------------------

#define GY 37                       // grid.y; 4*37 = 148 CTAs (1/SM)
#define BLOCK 256
#define SMEM_BYTES (3 * 65536)      // A 64KB + B double buffer 2x64KB

__device__ __align__(256) __half g_fB[65536 * 256];  // features fp16
__device__ __align__(256) __half g_fA[512 * 256];    // inputs fp16

// ---------------- convert: fp32 -> fp16 streaming ----------------
__global__ void __launch_bounds__(256) convert_kernel(
    const float* __restrict__ features, const float* __restrict__ inputs)
{
    const int stride = gridDim.x * blockDim.x;
    const float4* f4 = reinterpret_cast<const float4*>(features);
    uint2* b4 = reinterpret_cast<uint2*>(g_fB);
    for (int i = blockIdx.x * blockDim.x + threadIdx.x; i < 4194304; i += stride) {
        float4 v = f4[i];
        __half2 h0 = __floats2half2_rn(v.x, v.y);
        __half2 h1 = __floats2half2_rn(v.z, v.w);
        b4[i] = make_uint2(*reinterpret_cast<uint32_t*>(&h0),
                           *reinterpret_cast<uint32_t*>(&h1));
    }
    const float4* i4 = reinterpret_cast<const float4*>(inputs);
    uint2* a4 = reinterpret_cast<uint2*>(g_fA);
    for (int i = blockIdx.x * blockDim.x + threadIdx.x; i < 32768; i += stride) {
        float4 v = i4[i];
        __half2 h0 = __floats2half2_rn(v.x, v.y);
        __half2 h1 = __floats2half2_rn(v.z, v.w);
        a4[i] = make_uint2(*reinterpret_cast<uint32_t*>(&h0),
                           *reinterpret_cast<uint32_t*>(&h1));
    }
}

// ---------------- gemm helpers ----------------
__device__ __forceinline__ uint32_t smem_u32(const void* p) {
    uint32_t a;
    asm("{ .reg .u64 t; cvta.to.shared.u64 t, %1; cvt.u32.u64 %0, t; }"
        : "=r"(a) : "l"(p));
    return a;
}

// Row = 512B (256 halves). Swizzle: XOR 16B-chunk index with (row & 7).
__device__ __forceinline__ uint32_t swz(uint32_t off) {
    return off ^ (((off >> 9) & 7u) << 4);
}

__device__ __forceinline__ void cp16(uint32_t dst, const void* src) {
    asm volatile("cp.async.cg.shared.global [%0], [%1], 16;"
                 :: "r"(dst), "l"(src));
}

__device__ __forceinline__ void ldm_x4(uint32_t* r, uint32_t addr) {
    asm volatile(
        "ldmatrix.sync.aligned.m8n8.x4.shared.b16 {%0,%1,%2,%3}, [%4];"
        : "=r"(r[0]), "=r"(r[1]), "=r"(r[2]), "=r"(r[3]) : "r"(addr));
}

// f16-accumulate HMMA: D,C are 2 x f16x2 registers.
__device__ __forceinline__ void mma_16816_f16(uint32_t* c, const uint32_t* a,
                                              uint32_t b0, uint32_t b1) {
    asm volatile(
        "mma.sync.aligned.m16n8k16.row.col.f16.f16.f16.f16 "
        "{%0,%1}, {%2,%3,%4,%5}, {%6,%7}, {%0,%1};"
        : "+r"(c[0]), "+r"(c[1])
        : "r"(a[0]), "r"(a[1]), "r"(a[2]), "r"(a[3]), "r"(b0), "r"(b1));
}

__device__ __forceinline__ void stg_cs_v2(float* p, float x, float y) {
    asm volatile("st.global.cs.v2.f32 [%0], {%1, %2};"
                 :: "l"(p), "f"(x), "f"(y) : "memory");
}

// Issue cp.async for a full 128x256-half tile (64KB) into swizzled smem.
__device__ __forceinline__ void issue_tile_copy(uint32_t sdst,
                                                const __half* gsrc, int tid) {
#pragma unroll
    for (int q = tid; q < 4096; q += BLOCK) {
        int row = q >> 5;        // 32 x 16B chunks per 512B row
        int c   = q & 31;
        cp16(sdst + swz((uint32_t)(row * 512 + c * 16)),
             gsrc + row * 256 + c * 8);
    }
}

__global__ void __launch_bounds__(BLOCK, 1) gemm_kernel(float* __restrict__ out)
{
    extern __shared__ char smem[];
    const uint32_t sA  = smem_u32(smem);       // 128 x 512B
    const uint32_t sB0 = sA + 65536u;
    const uint32_t sB1 = sA + 131072u;

    const int tid = threadIdx.x;
    const int wid = tid >> 5;
    const int lid = tid & 31;
    const int wm = wid >> 2;    // 0..1  (64 m-rows each)
    const int wn = wid & 3;     // 0..3  (32 n-rows each)
    const int m_super = blockIdx.x;   // 0..3
    const int j0 = blockIdx.y;        // first n-block; stride GY

    // Prologue: A tile + first two B tiles in flight (3 commit groups).
    issue_tile_copy(sA, g_fA + m_super * 128 * 256, tid);
    asm volatile("cp.async.commit_group;");
    issue_tile_copy(sB0, g_fB + (size_t)j0 * 128 * 256, tid);
    asm volatile("cp.async.commit_group;");
    issue_tile_copy(sB1, g_fB + (size_t)(j0 + GY) * 128 * 256, tid);
    asm volatile("cp.async.commit_group;");

    // Per-lane ldmatrix address components
    const int a_row = lid & 15;
    const int a_kb  = (lid >> 4) * 16;                 // bytes
    const int b_row = (lid & 7) + ((lid >> 4) * 8);
    const int b_kb  = ((lid >> 3) & 1) * 16;           // bytes

    int parity = 0;
    for (int j = j0; j < 512; j += GY) {
        asm volatile("cp.async.wait_group 1;");
        __syncthreads();
        const uint32_t sB = parity ? sB1 : sB0;

        float acc[4][4][4];        // f32 master accumulators
        uint32_t c16[4][4][2];     // fp16 chain accumulators (f16x2 pairs)
#pragma unroll
        for (int mf = 0; mf < 4; ++mf)
#pragma unroll
            for (int nf = 0; nf < 4; ++nf) {
#pragma unroll
                for (int e = 0; e < 4; ++e) acc[mf][nf][e] = 0.0f;
                c16[mf][nf][0] = 0u;
                c16[mf][nf][1] = 0u;
            }

#pragma unroll
        for (int ks = 0; ks < 16; ++ks) {
            const uint32_t kb = (uint32_t)ks * 32;
            uint32_t a[4][4];
#pragma unroll
            for (int mf = 0; mf < 4; ++mf) {
                int row = wm * 64 + mf * 16 + a_row;
                ldm_x4(a[mf], sA + swz((uint32_t)(row * 512) + kb + a_kb));
            }
            uint32_t b[2][4];
#pragma unroll
            for (int ng = 0; ng < 2; ++ng) {
                int nrow = wn * 32 + ng * 16 + b_row;
                ldm_x4(b[ng], sB + swz((uint32_t)(nrow * 512) + kb + b_kb));
            }
#pragma unroll
            for (int mf = 0; mf < 4; ++mf)
#pragma unroll
                for (int nf = 0; nf < 4; ++nf)
                    mma_16816_f16(c16[mf][nf], a[mf],
                                  b[nf >> 1][(nf & 1) * 2 + 0],
                                  b[nf >> 1][(nf & 1) * 2 + 1]);

            // Fold fp16 chains into f32 every 2 k-steps (chunk K=32).
            if (ks & 1) {
#pragma unroll
                for (int mf = 0; mf < 4; ++mf)
#pragma unroll
                    for (int nf = 0; nf < 4; ++nf) {
                        float2 lo = __half22float2(
                            *reinterpret_cast<__half2*>(&c16[mf][nf][0]));
                        float2 hi = __half22float2(
                            *reinterpret_cast<__half2*>(&c16[mf][nf][1]));
                        acc[mf][nf][0] += lo.x;
                        acc[mf][nf][1] += lo.y;
                        acc[mf][nf][2] += hi.x;
                        acc[mf][nf][3] += hi.y;
                        c16[mf][nf][0] = 0u;
                        c16[mf][nf][1] = 0u;
                    }
            }
        }

        __syncthreads();   // all warps done reading sB(parity)

        // Prefetch B tile j + 2*GY into the freed buffer.
        int pf = j + 2 * GY;
        if (pf < 512)
            issue_tile_copy(parity ? sB1 : sB0,
                            g_fB + (size_t)pf * 128 * 256, tid);
        asm volatile("cp.async.commit_group;");

        // Epilogue: streaming GMEM float2 stores
        const int row0 = m_super * 128 + wm * 64 + (lid >> 2);
        const int col0 = j * 128 + wn * 32 + (lid & 3) * 2;
#pragma unroll
        for (int mf = 0; mf < 4; ++mf) {
#pragma unroll
            for (int nf = 0; nf < 4; ++nf) {
                const int r = row0 + mf * 16;
                const int c = col0 + nf * 8;
                stg_cs_v2(out + (size_t)r * 65536 + c,
                          acc[mf][nf][0], acc[mf][nf][1]);
                stg_cs_v2(out + (size_t)(r + 8) * 65536 + c,
                          acc[mf][nf][2], acc[mf][nf][3]);
            }
        }
        parity ^= 1;
    }
}

extern "C" void kernel_launch(void* const* d_in, const int* in_sizes, int n_in,
                              void* d_out, int out_size) {
    // metadata order: inputs f32[512,256], indexes i64[512],
    //                 features f32[65536,256], mIoU f32[65536], IoU f32[512];
    //                 output f32[512,65536]
    const float* inputs   = (const float*)d_in[0];
    const float* features = (const float*)d_in[2];
    float* out = (float*)d_out;

    convert_kernel<<<1184, 256>>>(features, inputs);

    cudaFuncSetAttribute(gemm_kernel,
                         cudaFuncAttributeMaxDynamicSharedMemorySize, SMEM_BYTES);
    // grid.x = m_super (fast): the 4 CTAs sharing each B tile run concurrently
    gemm_kernel<<<dim3(4, GY), BLOCK, SMEM_BYTES>>>(out);
}

// round 14
// speedup vs baseline: 1.1244x; 1.1244x over previous
#include <cuda_runtime.h>
#include <cuda_fp16.h>
#include <cstdint>

// ---------------------------------------------------------------------------
// out[512, 65536] = inputs[512,256] @ features[65536,256]^T   (fp32 in/out)
//
// Toolchain: compute_103 virtual arch -> no tcgen05; tensor path is
// ldmatrix + mma.sync.m16n8k16 f32-accum (HMMA, rt~16cyc/SMSP; f16-accum
// probe R13 showed equal rate). Mainloop floor ~59us.
//
// R14: single kernel, in-CTA warp specialization with correct priorities.
//   148 CTAs x 384 threads:
//   - warps 4..11 (HIGH wid = high arbiter priority): 8 MMA warps, 2/SMSP.
//     CTA tile M=128 x N=64 x K=256; warp tile 64x32 with k-split x2
//     (pairs kh=0/1 each do K=128), acc=64 regs; smem k-reduction epilogue.
//   - warps 0..3 (LOW priority): converters. Stream fp32 B slabs via
//     cp.async into a 64KB smem staging buffer, LDS+cvt+STS fp16 into the
//     ping-pong compute buffers. fp32 B read from DRAM exactly once
//     (L2-shared by the 4 m_super CTAs); fp16 B never touches DRAM.
//   A (inputs stripe) converted in the prologue.
// ---------------------------------------------------------------------------

#define BLOCK 384
#define SMEM_BYTES 196608   // A 64KB + fp16 B 2x32KB + fp32 staging 64KB

__device__ __forceinline__ uint32_t smem_u32(const void* p) {
    uint32_t a;
    asm("{ .reg .u64 t; cvta.to.shared.u64 t, %1; cvt.u32.u64 %0, t; }"
        : "=r"(a) : "l"(p));
    return a;
}

// fp16 rows of 512B; XOR 16B-chunk index with (row & 7).
__device__ __forceinline__ uint32_t swz(uint32_t off) {
    return off ^ (((off >> 9) & 7u) << 4);
}

__device__ __forceinline__ void cp16(uint32_t dst, const void* src) {
    asm volatile("cp.async.cg.shared.global [%0], [%1], 16;"
                 :: "r"(dst), "l"(src));
}

__device__ __forceinline__ void ldm_x4(uint32_t* r, uint32_t addr) {
    asm volatile(
        "ldmatrix.sync.aligned.m8n8.x4.shared.b16 {%0,%1,%2,%3}, [%4];"
        : "=r"(r[0]), "=r"(r[1]), "=r"(r[2]), "=r"(r[3]) : "r"(addr));
}

__device__ __forceinline__ void mma_16816(float* c, const uint32_t* a,
                                          uint32_t b0, uint32_t b1) {
    asm volatile(
        "mma.sync.aligned.m16n8k16.row.col.f32.f16.f16.f32 "
        "{%0,%1,%2,%3}, {%4,%5,%6,%7}, {%8,%9}, {%0,%1,%2,%3};"
        : "+f"(c[0]), "+f"(c[1]), "+f"(c[2]), "+f"(c[3])
        : "r"(a[0]), "r"(a[1]), "r"(a[2]), "r"(a[3]), "r"(b0), "r"(b1));
}

__device__ __forceinline__ void stg_cs_v2(float* p, float x, float y) {
    asm volatile("st.global.cs.v2.f32 [%0], {%1, %2};"
                 :: "l"(p), "f"(x), "f"(y) : "memory");
}

// Convert one float4 to 4 halves and store 8B to smem.
__device__ __forceinline__ void cvt_sts(uint32_t smem_addr, float4 v) {
    __half2 h0 = __floats2half2_rn(v.x, v.y);
    __half2 h1 = __floats2half2_rn(v.z, v.w);
    asm volatile("st.shared.v2.b32 [%0], {%1, %2};"
                 :: "r"(smem_addr),
                    "r"(*reinterpret_cast<uint32_t*>(&h0)),
                    "r"(*reinterpret_cast<uint32_t*>(&h1)));
}

// Converter warp w: cp.async its 16 rows (16KB) of a fp32 slab into sF.
__device__ __forceinline__ void conv_cp_slab(uint32_t sF, const float* g,
                                             int w, int lid) {
#pragma unroll
    for (int t = 0; t < 32; ++t) {
        int q  = w * 1024 + t * 32 + lid;   // 16B-chunk index (4096/slab)
        int n  = q >> 6;
        int cc = q & 63;
        cp16(sF + (uint32_t)(n * 1024 + cc * 16), g + n * 256 + cc * 4);
    }
}

// Converter warp w: LDS fp32 rows 16w..16w+15 from sF, cvt, STS fp16 -> sH.
__device__ __forceinline__ void conv_convert(uint32_t sF, uint32_t sH,
                                             int w, int lid) {
#pragma unroll
    for (int t = 0; t < 32; ++t) {
        int n  = w * 16 + (t >> 1);
        int cc = (t & 1) * 32 + lid;        // float4 index within row
        float4 v;
        asm volatile("ld.shared.v4.f32 {%0,%1,%2,%3}, [%4];"
                     : "=f"(v.x), "=f"(v.y), "=f"(v.z), "=f"(v.w)
                     : "r"(sF + (uint32_t)(n * 1024 + cc * 16)));
        cvt_sts(sH + swz((uint32_t)(n * 512 + cc * 8)), v);
    }
}

__global__ void __launch_bounds__(BLOCK, 1) gemm_kernel(
    const float* __restrict__ inputs,    // [512, 256]
    const float* __restrict__ features,  // [65536, 256]
    float* __restrict__ out)             // [512, 65536]
{
    extern __shared__ char smem[];
    const uint32_t sA  = smem_u32(smem);    // 64KB fp16 A
    const uint32_t sH0 = sA + 65536u;       // 32KB fp16 B ping
    const uint32_t sH1 = sA + 98304u;       // 32KB fp16 B pong
    const uint32_t sF  = sA + 131072u;      // 64KB fp32 staging

    const int tid = threadIdx.x;
    const int wid = tid >> 5;
    const int lid = tid & 31;
    const int m_super = blockIdx.x;   // 0..3
    const int j0 = blockIdx.y;        // slab stream j0 + k*37, slabs 0..1023

    // ---- Prologue ----
    if (wid < 4)   // converters: start fetching fp32 slab j0 immediately
        conv_cp_slab(sF, features + (size_t)j0 * 64 * 256, wid, lid);
    asm volatile("cp.async.commit_group;");

    // all warps: convert A stripe fp32 -> fp16 smem
    {
        const float4* Ag = reinterpret_cast<const float4*>(inputs)
                         + m_super * 8192;
        for (int q = tid; q < 8192; q += BLOCK) {
            float4 v = __ldg(Ag + q);
            int row = q >> 6;
            int c4  = q & 63;
            cvt_sts(sA + swz((uint32_t)(row * 512 + c4 * 8)), v);
        }
    }

    if (wid < 4) {
        asm volatile("cp.async.wait_group 0;");
        conv_convert(sF, sH0, wid, lid);          // slab j0 -> ping buffer
        if (j0 + 37 < 1024)
            conv_cp_slab(sF, features + (size_t)(j0 + 37) * 64 * 256,
                         wid, lid);
        asm volatile("cp.async.commit_group;");
    }
    __syncthreads();

    // MMA warp coordinates
    const int cw = wid - 4;            // 0..7 (valid for wid>=4)
    const int kh = cw >> 2;            // k-half
    const int wm = (cw & 3) >> 1;      // 0..1 (64 m-rows)
    const int wn = cw & 1;             // 0..1 (32 n-cols)
    const int pid = cw & 3;            // reduction pair id

    const int a_row = lid & 15;
    const int a_kb  = (lid >> 4) * 16;
    const int b_row = (lid & 7) + ((lid >> 4) * 8);
    const int b_kb  = ((lid >> 3) & 1) * 16;

    int parity = 0;
    for (int jv = j0; jv < 1024; jv += 37) {
        const uint32_t sHc = parity ? sH1 : sH0;   // compute buffer
        const uint32_t sHn = parity ? sH0 : sH1;   // fill buffer

        if (wid < 4) {
            // ---- converter warps: produce fp16 slab jv+37 ----
            if (jv + 37 < 1024) {
                asm volatile("cp.async.wait_group 0;");
                conv_convert(sF, sHn, wid, lid);
                if (jv + 74 < 1024)
                    conv_cp_slab(sF, features + (size_t)(jv + 74) * 64 * 256,
                                 wid, lid);
                asm volatile("cp.async.commit_group;");
            }
        } else {
            // ---- MMA warps: 8 k-steps on this warp's k-half ----
            float acc[4][4][4];
#pragma unroll
            for (int mf = 0; mf < 4; ++mf)
#pragma unroll
                for (int nf = 0; nf < 4; ++nf)
#pragma unroll
                    for (int e = 0; e < 4; ++e) acc[mf][nf][e] = 0.0f;

#pragma unroll
            for (int ks = 0; ks < 8; ++ks) {
                const uint32_t kb = (uint32_t)(kh * 8 + ks) * 32;
                uint32_t a[4][4];
#pragma unroll
                for (int mf = 0; mf < 4; ++mf) {
                    int row = wm * 64 + mf * 16 + a_row;
                    ldm_x4(a[mf], sA + swz((uint32_t)(row * 512) + kb + a_kb));
                }
                uint32_t b[2][4];
#pragma unroll
                for (int ng = 0; ng < 2; ++ng) {
                    int nrow = wn * 32 + ng * 16 + b_row;
                    ldm_x4(b[ng], sHc + swz((uint32_t)(nrow * 512) + kb + b_kb));
                }
#pragma unroll
                for (int mf = 0; mf < 4; ++mf)
#pragma unroll
                    for (int nf = 0; nf < 4; ++nf)
                        mma_16816(acc[mf][nf], a[mf],
                                  b[nf >> 1][(nf & 1) * 2 + 0],
                                  b[nf >> 1][(nf & 1) * 2 + 1]);
            }

            // ---- k-reduction: kh=1 stores to scratch (in sHc, now free),
            //      kh=0 adds and writes out. MMA-only named barrier. ----
            asm volatile("bar.sync 1, 256;" ::: "memory");
            const uint32_t scratch = sHc + (uint32_t)pid * 8192u;
            if (kh == 1) {
#pragma unroll
                for (int i = 0; i < 16; ++i) {
                    const float* s = acc[i >> 2][i & 3];
                    asm volatile("st.shared.v4.f32 [%0], {%1,%2,%3,%4};"
                                 :: "r"(scratch + (uint32_t)(i * 512 + lid * 16)),
                                    "f"(s[0]), "f"(s[1]), "f"(s[2]), "f"(s[3]));
                }
            }
            asm volatile("bar.sync 1, 256;" ::: "memory");
            if (kh == 0) {
                const int row0 = m_super * 128 + wm * 64 + (lid >> 2);
                const int col0 = jv * 64 + wn * 32 + (lid & 3) * 2;
#pragma unroll
                for (int i = 0; i < 16; ++i) {
                    float4 v;
                    asm volatile("ld.shared.v4.f32 {%0,%1,%2,%3}, [%4];"
                                 : "=f"(v.x), "=f"(v.y), "=f"(v.z), "=f"(v.w)
                                 : "r"(scratch + (uint32_t)(i * 512 + lid * 16)));
                    float* s = acc[i >> 2][i & 3];
                    const int r = row0 + (i >> 2) * 16;
                    const int c = col0 + (i & 3) * 8;
                    stg_cs_v2(out + (size_t)r * 65536 + c,
                              s[0] + v.x, s[1] + v.y);
                    stg_cs_v2(out + (size_t)(r + 8) * 65536 + c,
                              s[2] + v.z, s[3] + v.w);
                }
            }
        }
        __syncthreads();   // fp16[p^1] ready; sHc reads/scratch done
        parity ^= 1;
    }
}

extern "C" void kernel_launch(void* const* d_in, const int* in_sizes, int n_in,
                              void* d_out, int out_size) {
    // metadata order: inputs f32[512,256], indexes i64[512],
    //                 features f32[65536,256], mIoU f32[65536], IoU f32[512];
    //                 output f32[512,65536]
    const float* inputs   = (const float*)d_in[0];
    const float* features = (const float*)d_in[2];
    float* out = (float*)d_out;

    cudaFuncSetAttribute(gemm_kernel,
                         cudaFuncAttributeMaxDynamicSharedMemorySize, SMEM_BYTES);
    // grid.x = m_super (fast): the 4 CTAs sharing each fp32 slab run together
    gemm_kernel<<<dim3(4, 37), BLOCK, SMEM_BYTES>>>(inputs, features, out);
}

// round 15
// speedup vs baseline: 1.1994x; 1.0667x over previous
#include <cuda_runtime.h>
#include <cuda_fp16.h>
#include <cstdint>

// ---------------------------------------------------------------------------
// out[512, 65536] = inputs[512,256] @ features[65536,256]^T   (fp32 in/out)
//
// Toolchain: compute_103 virtual arch -> no tcgen05; tensor path is
// ldmatrix + mma.sync.m16n8k16 f32-accum (rt~16cyc/SMSP; floor ~59.5us).
//
// R15 = R9's fused LDG(fp32)->cvt->STS pipeline with the register budget
// fixed: warp tile 32x32 (acc = 32 regs, 8 warps as 4m x 2n on an
// M=128 x N=64 CTA tile) frees room for 8-float4 staging batches
// (issue b0@ks0, consume@ks7, issue b1@ks8, consume after ks15).
// ~165 regs total -> no spills (R9 failure mode), same HMMA floor.
// fp32 B read once from DRAM (L2-shared by the 4 m_super CTAs); fp16 B
// exists only in smem. Single kernel, no separate convert pass.
// ---------------------------------------------------------------------------

#define BLOCK 256
#define SMEM_BYTES (65536 + 2 * 32768)  // A 64KB + fp16 B ping-pong 2x32KB

__device__ __forceinline__ uint32_t smem_u32(const void* p) {
    uint32_t a;
    asm("{ .reg .u64 t; cvta.to.shared.u64 t, %1; cvt.u32.u64 %0, t; }"
        : "=r"(a) : "l"(p));
    return a;
}

// fp16 rows of 512B; XOR 16B-chunk index with (row & 7).
__device__ __forceinline__ uint32_t swz(uint32_t off) {
    return off ^ (((off >> 9) & 7u) << 4);
}

__device__ __forceinline__ void ldm_x4(uint32_t* r, uint32_t addr) {
    asm volatile(
        "ldmatrix.sync.aligned.m8n8.x4.shared.b16 {%0,%1,%2,%3}, [%4];"
        : "=r"(r[0]), "=r"(r[1]), "=r"(r[2]), "=r"(r[3]) : "r"(addr));
}

__device__ __forceinline__ void mma_16816(float* c, const uint32_t* a,
                                          uint32_t b0, uint32_t b1) {
    asm volatile(
        "mma.sync.aligned.m16n8k16.row.col.f32.f16.f16.f32 "
        "{%0,%1,%2,%3}, {%4,%5,%6,%7}, {%8,%9}, {%0,%1,%2,%3};"
        : "+f"(c[0]), "+f"(c[1]), "+f"(c[2]), "+f"(c[3])
        : "r"(a[0]), "r"(a[1]), "r"(a[2]), "r"(a[3]), "r"(b0), "r"(b1));
}

__device__ __forceinline__ void stg_cs_v2(float* p, float x, float y) {
    asm volatile("st.global.cs.v2.f32 [%0], {%1, %2};"
                 :: "l"(p), "f"(x), "f"(y) : "memory");
}

// Convert one float4 to 4 halves and store 8B to swizzled smem.
__device__ __forceinline__ void cvt_sts(uint32_t smem_addr, float4 v) {
    __half2 h0 = __floats2half2_rn(v.x, v.y);
    __half2 h1 = __floats2half2_rn(v.z, v.w);
    asm volatile("st.shared.v2.b32 [%0], {%1, %2};"
                 :: "r"(smem_addr),
                    "r"(*reinterpret_cast<uint32_t*>(&h0)),
                    "r"(*reinterpret_cast<uint32_t*>(&h1)));
}

__global__ void __launch_bounds__(BLOCK, 1) gemm_kernel(
    const float* __restrict__ inputs,    // [512, 256]
    const float* __restrict__ features,  // [65536, 256]
    float* __restrict__ out)             // [512, 65536]
{
    extern __shared__ char smem[];
    const uint32_t sA  = smem_u32(smem);   // 64KB fp16 A
    const uint32_t sB0 = sA + 65536u;      // 32KB fp16 B ping
    const uint32_t sB1 = sA + 98304u;      // 32KB fp16 B pong

    const int tid = threadIdx.x;
    const int wid = tid >> 5;
    const int lid = tid & 31;
    const int wm  = wid >> 1;     // 0..3  (32 m-rows)
    const int wn  = wid & 1;      // 0..1  (32 n-cols)
    const int m_super = blockIdx.x;   // 0..3
    const int j0 = blockIdx.y;        // slab stream: j0 + k*37, slabs 0..1023

    // ---- Prologue: convert A stripe (128 x 256 fp32 -> fp16 smem) ----
    {
        const float4* Ag = reinterpret_cast<const float4*>(inputs)
                         + m_super * 8192;
#pragma unroll 8
        for (int it = 0; it < 32; ++it) {
            int fi = it * 256 + tid;
            float4 v = __ldg(Ag + fi);
            int row = fi >> 6;                 // 64 float4 per row
            int c4  = fi & 63;
            cvt_sts(sA + swz((uint32_t)(row * 512 + c4 * 8)), v);
        }
    }
    // ---- Prologue: convert slab j0 (64 x 256 fp32) into ping buffer ----
    {
        const float4* Bg = reinterpret_cast<const float4*>(features)
                         + (size_t)j0 * 4096;
#pragma unroll 8
        for (int it = 0; it < 16; ++it) {
            int fi = it * 256 + tid;
            float4 v = __ldg(Bg + fi);
            int row = fi >> 6;
            int c4  = fi & 63;
            cvt_sts(sB0 + swz((uint32_t)(row * 512 + c4 * 8)), v);
        }
    }
    __syncthreads();

    // Per-lane ldmatrix address components
    const int a_row = lid & 15;
    const int a_kb  = (lid >> 4) * 16;
    const int b_row = (lid & 7) + ((lid >> 4) * 8);
    const int b_kb  = ((lid >> 3) & 1) * 16;
    // Per-thread STS placement for staged conversions:
    //   float4 fi = it*256 + tid; row = it*4 + (tid>>6), c4 = tid&63
    const int srow4 = tid >> 6;          // 0..3
    const int sc4   = tid & 63;

    int parity = 0;
    for (int jv = j0; jv < 1024; jv += 37) {
        const bool has_nxt = (jv + 37) < 1024;
        const float4* src = reinterpret_cast<const float4*>(features)
                          + (size_t)(jv + 37) * 4096;
        const uint32_t sBc = parity ? sB1 : sB0;        // compute buffer
        const uint32_t sBn = parity ? sB0 : sB1;        // fill buffer

        float acc[2][4][4];
#pragma unroll
        for (int mf = 0; mf < 2; ++mf)
#pragma unroll
            for (int nf = 0; nf < 4; ++nf)
#pragma unroll
                for (int e = 0; e < 4; ++e) acc[mf][nf][e] = 0.0f;

        float4 stage[8];   // one 8-float4 batch in flight (32 regs)

#pragma unroll
        for (int ks = 0; ks < 16; ++ks) {
            if (has_nxt) {
                if (ks == 0) {               // issue batch 0 (its 0..7)
#pragma unroll
                    for (int r = 0; r < 8; ++r)
                        stage[r] = __ldg(src + r * 256 + tid);
                } else if (ks == 7) {        // consume batch 0
#pragma unroll
                    for (int r = 0; r < 8; ++r) {
                        uint32_t off =
                            (uint32_t)((r * 4 + srow4) * 512 + sc4 * 8);
                        cvt_sts(sBn + swz(off), stage[r]);
                    }
                } else if (ks == 8) {        // issue batch 1 (its 8..15)
#pragma unroll
                    for (int r = 0; r < 8; ++r)
                        stage[r] = __ldg(src + (8 + r) * 256 + tid);
                }
            }

            const uint32_t kb = (uint32_t)ks * 32;
            uint32_t a[2][4];
#pragma unroll
            for (int mf = 0; mf < 2; ++mf) {
                int row = wm * 32 + mf * 16 + a_row;
                ldm_x4(a[mf], sA + swz((uint32_t)(row * 512) + kb + a_kb));
            }
            uint32_t b[2][4];
#pragma unroll
            for (int ng = 0; ng < 2; ++ng) {
                int nrow = wn * 32 + ng * 16 + b_row;
                ldm_x4(b[ng], sBc + swz((uint32_t)(nrow * 512) + kb + b_kb));
            }
#pragma unroll
            for (int mf = 0; mf < 2; ++mf)
#pragma unroll
                for (int nf = 0; nf < 4; ++nf)
                    mma_16816(acc[mf][nf], a[mf],
                              b[nf >> 1][(nf & 1) * 2 + 0],
                              b[nf >> 1][(nf & 1) * 2 + 1]);
        }

        // Consume batch 1 (its 8..15) into the fill buffer.
        if (has_nxt) {
#pragma unroll
            for (int r = 0; r < 8; ++r) {
                uint32_t off =
                    (uint32_t)(((8 + r) * 4 + srow4) * 512 + sc4 * 8);
                cvt_sts(sBn + swz(off), stage[r]);
            }
        }

        __syncthreads();   // sBc reads + sBn writes complete CTA-wide

        // Epilogue: streaming GMEM float2 stores
        const int row0 = m_super * 128 + wm * 32 + (lid >> 2);
        const int col0 = jv * 64 + wn * 32 + (lid & 3) * 2;
#pragma unroll
        for (int mf = 0; mf < 2; ++mf) {
#pragma unroll
            for (int nf = 0; nf < 4; ++nf) {
                const int r = row0 + mf * 16;
                const int c = col0 + nf * 8;
                stg_cs_v2(out + (size_t)r * 65536 + c,
                          acc[mf][nf][0], acc[mf][nf][1]);
                stg_cs_v2(out + (size_t)(r + 8) * 65536 + c,
                          acc[mf][nf][2], acc[mf][nf][3]);
            }
        }
        parity ^= 1;
    }
}

extern "C" void kernel_launch(void* const* d_in, const int* in_sizes, int n_in,
                              void* d_out, int out_size) {
    // metadata order: inputs f32[512,256], indexes i64[512],
    //                 features f32[65536,256], mIoU f32[65536], IoU f32[512];
    //                 output f32[512,65536]
    const float* inputs   = (const float*)d_in[0];
    const float* features = (const float*)d_in[2];
    float* out = (float*)d_out;

    cudaFuncSetAttribute(gemm_kernel,
                         cudaFuncAttributeMaxDynamicSharedMemorySize, SMEM_BYTES);
    // grid.x = m_super (fast): the 4 CTAs sharing each fp32 slab run together
    gemm_kernel<<<dim3(4, 37), BLOCK, SMEM_BYTES>>>(inputs, features, out);
}

// round 16
// speedup vs baseline: 1.2003x; 1.0008x over previous
#include <cuda_runtime.h>
#include <cuda_fp16.h>
#include <cstdint>

// ---------------------------------------------------------------------------
// out[512, 65536] = inputs[512,256] @ features[65536,256]^T   (fp32 in/out)
//
// Toolchain: compute_103 virtual arch -> no tcgen05; tensor path is
// ldmatrix + mma.sync.m16n8k16 f32-accum. Measured across 7 schedules:
// gemm floor ~59us (HMMA issue-limited); fusing the fp32->fp16 convert into
// the gemm's SMs always costs >= the ~16us it saves. So: best-measured gemm
// (R8: ping-pong 128-thread halves, warp tile 64x32) kept verbatim, plus a
// bandwidth-tuned standalone convert:
//   - fp32 features read with ld.global.cs (evict-first; never re-read)
//   - fp16 writes normal priority -> B sits warm in L2 (32MB << 126MB)
//     for the gemm's cp.async stream
//   - grid 592 x 256 (4 CTAs/SM), flat unrolled grid-stride for MLP
//   - A conversion moved into the gemm prologue (one less dependency)
// ---------------------------------------------------------------------------

#define GY 37                            // gemm grid (4, 37) = 148 CTAs
#define BLOCK 256
#define SMEM_BYTES (65536 + 4 * 32768)   // A 64KB + 2 halves x 2 x 32KB

__device__ __align__(256) __half g_fB[65536 * 256];  // features fp16

// ---------------- convert: fp32 features -> fp16, streaming ----------------
__global__ void __launch_bounds__(256) convert_kernel(
    const float* __restrict__ features)
{
    // 65536*256 floats = 4194304 float4. 592 CTAs x 256 thr -> 27.7 f4/thr.
    const float4* f4 = reinterpret_cast<const float4*>(features);
    uint2* b4 = reinterpret_cast<uint2*>(g_fB);
    const int base = blockIdx.x * 256 + threadIdx.x;
    const int stride = gridDim.x * 256;      // 151552
#pragma unroll 7
    for (int it = 0; it < 27; ++it) {
        int i = base + it * stride;
        float4 v;
        asm volatile("ld.global.cs.v4.f32 {%0,%1,%2,%3}, [%4];"
                     : "=f"(v.x), "=f"(v.y), "=f"(v.z), "=f"(v.w)
                     : "l"(f4 + i));
        __half2 h0 = __floats2half2_rn(v.x, v.y);
        __half2 h1 = __floats2half2_rn(v.z, v.w);
        b4[i] = make_uint2(*reinterpret_cast<uint32_t*>(&h0),
                           *reinterpret_cast<uint32_t*>(&h1));
    }
    {   // tail: indices >= 27*stride
        int i = base + 27 * stride;
        if (i < 4194304) {
            float4 v;
            asm volatile("ld.global.cs.v4.f32 {%0,%1,%2,%3}, [%4];"
                         : "=f"(v.x), "=f"(v.y), "=f"(v.z), "=f"(v.w)
                         : "l"(f4 + i));
            __half2 h0 = __floats2half2_rn(v.x, v.y);
            __half2 h1 = __floats2half2_rn(v.z, v.w);
            b4[i] = make_uint2(*reinterpret_cast<uint32_t*>(&h0),
                               *reinterpret_cast<uint32_t*>(&h1));
        }
    }
}

// ---------------- gemm helpers ----------------
__device__ __forceinline__ uint32_t smem_u32(const void* p) {
    uint32_t a;
    asm("{ .reg .u64 t; cvta.to.shared.u64 t, %1; cvt.u32.u64 %0, t; }"
        : "=r"(a) : "l"(p));
    return a;
}

// Rows are 512B (256 halves). Swizzle: XOR 16B-chunk index with (row & 7).
__device__ __forceinline__ uint32_t swz(uint32_t off) {
    return off ^ (((off >> 9) & 7u) << 4);
}

__device__ __forceinline__ void cp16(uint32_t dst, const void* src) {
    asm volatile("cp.async.cg.shared.global [%0], [%1], 16;"
                 :: "r"(dst), "l"(src));
}

__device__ __forceinline__ void ldm_x4(uint32_t* r, uint32_t addr) {
    asm volatile(
        "ldmatrix.sync.aligned.m8n8.x4.shared.b16 {%0,%1,%2,%3}, [%4];"
        : "=r"(r[0]), "=r"(r[1]), "=r"(r[2]), "=r"(r[3]) : "r"(addr));
}

__device__ __forceinline__ void mma_16816(float* c, const uint32_t* a,
                                          uint32_t b0, uint32_t b1) {
    asm volatile(
        "mma.sync.aligned.m16n8k16.row.col.f32.f16.f16.f32 "
        "{%0,%1,%2,%3}, {%4,%5,%6,%7}, {%8,%9}, {%0,%1,%2,%3};"
        : "+f"(c[0]), "+f"(c[1]), "+f"(c[2]), "+f"(c[3])
        : "r"(a[0]), "r"(a[1]), "r"(a[2]), "r"(a[3]), "r"(b0), "r"(b1));
}

__device__ __forceinline__ void stg_cs_v2(float* p, float x, float y) {
    asm volatile("st.global.cs.v2.f32 [%0], {%1, %2};"
                 :: "l"(p), "f"(x), "f"(y) : "memory");
}

__device__ __forceinline__ void cvt_sts(uint32_t smem_addr, float4 v) {
    __half2 h0 = __floats2half2_rn(v.x, v.y);
    __half2 h1 = __floats2half2_rn(v.z, v.w);
    asm volatile("st.shared.v2.b32 [%0], {%1, %2};"
                 :: "r"(smem_addr),
                    "r"(*reinterpret_cast<uint32_t*>(&h0)),
                    "r"(*reinterpret_cast<uint32_t*>(&h1)));
}

// B slab: 64 n-rows x 256 halves (32KB); issued by one 128-thread half.
__device__ __forceinline__ void issue_B(uint32_t sB, const __half* g, int htid) {
#pragma unroll
    for (int q = htid; q < 2048; q += 128) {
        int row = q >> 5;
        int c   = q & 31;
        cp16(sB + swz((uint32_t)(row * 512 + c * 16)), g + row * 256 + c * 8);
    }
}

__global__ void __launch_bounds__(BLOCK, 1) gemm_kernel(
    const float* __restrict__ inputs,    // [512, 256]
    float* __restrict__ out)             // [512, 65536]
{
    extern __shared__ char smem[];
    const uint32_t sA = smem_u32(smem);                 // 64KB shared A

    const int tid  = threadIdx.x;
    const int wid  = tid >> 5;
    const int lid  = tid & 31;
    const int half = wid >> 2;          // 0 or 1
    const int hw   = wid & 3;           // warp within half
    const int htid = tid & 127;
    const int wm   = hw >> 1;           // 0..1 (64 m-rows)
    const int wn   = hw & 1;            // 0..1 (32 n-rows)
    const int m_super = blockIdx.x;     // 0..3
    // n-block (64-wide) stream for this half: jb0 + i*74, jb < 1024
    const int jb0 = blockIdx.y * 2 + half;

    const uint32_t sBh = sA + 65536u + (uint32_t)half * 65536u;  // 2x32KB

    // Prologue: convert A stripe fp32 -> fp16 smem (all 256 threads),
    // then this half's first two B slabs via cp.async.
    {
        const float4* Ag = reinterpret_cast<const float4*>(inputs)
                         + m_super * 8192;
#pragma unroll 8
        for (int it = 0; it < 32; ++it) {
            int fi = it * 256 + tid;
            float4 v = __ldg(Ag + fi);
            int row = fi >> 6;
            int c4  = fi & 63;
            cvt_sts(sA + swz((uint32_t)(row * 512 + c4 * 8)), v);
        }
    }
    issue_B(sBh, g_fB + (size_t)jb0 * 64 * 256, htid);
    asm volatile("cp.async.commit_group;");
    if (jb0 + 74 < 1024)
        issue_B(sBh + 32768u, g_fB + (size_t)(jb0 + 74) * 64 * 256, htid);
    asm volatile("cp.async.commit_group;");

    __syncthreads();                          // A visible CTA-wide

    // Per-lane ldmatrix address components
    const int a_row = lid & 15;
    const int a_kb  = (lid >> 4) * 16;
    const int b_row = (lid & 7) + ((lid >> 4) * 8);
    const int b_kb  = ((lid >> 3) & 1) * 16;
    const int bar_id = 1 + half;

    int parity = 0;
    for (int jb = jb0; jb < 1024; jb += 74) {
        asm volatile("cp.async.wait_group 1;");
        asm volatile("bar.sync %0, 128;" :: "r"(bar_id) : "memory");
        const uint32_t sB = sBh + (uint32_t)parity * 32768u;

        float acc[4][4][4];
#pragma unroll
        for (int mf = 0; mf < 4; ++mf)
#pragma unroll
            for (int nf = 0; nf < 4; ++nf)
#pragma unroll
                for (int e = 0; e < 4; ++e) acc[mf][nf][e] = 0.0f;

#pragma unroll
        for (int ks = 0; ks < 16; ++ks) {
            const uint32_t kb = (uint32_t)ks * 32;
            uint32_t a[4][4];
#pragma unroll
            for (int mf = 0; mf < 4; ++mf) {
                int row = wm * 64 + mf * 16 + a_row;
                ldm_x4(a[mf], sA + swz((uint32_t)(row * 512) + kb + a_kb));
            }
            uint32_t b[2][4];
#pragma unroll
            for (int ng = 0; ng < 2; ++ng) {
                int nrow = wn * 32 + ng * 16 + b_row;
                ldm_x4(b[ng], sB + swz((uint32_t)(nrow * 512) + kb + b_kb));
            }
#pragma unroll
            for (int mf = 0; mf < 4; ++mf)
#pragma unroll
                for (int nf = 0; nf < 4; ++nf)
                    mma_16816(acc[mf][nf], a[mf],
                              b[nf >> 1][(nf & 1) * 2 + 0],
                              b[nf >> 1][(nf & 1) * 2 + 1]);
        }

        asm volatile("bar.sync %0, 128;" :: "r"(bar_id) : "memory");

        // Prefetch slab jb+148 into the buffer this half just finished.
        if (jb + 148 < 1024)
            issue_B(sB, g_fB + (size_t)(jb + 148) * 64 * 256, htid);
        asm volatile("cp.async.commit_group;");

        // Epilogue: streaming GMEM float2 stores
        const int row0 = m_super * 128 + wm * 64 + (lid >> 2);
        const int col0 = jb * 64 + wn * 32 + (lid & 3) * 2;
#pragma unroll
        for (int mf = 0; mf < 4; ++mf) {
#pragma unroll
            for (int nf = 0; nf < 4; ++nf) {
                const int r = row0 + mf * 16;
                const int c = col0 + nf * 8;
                stg_cs_v2(out + (size_t)r * 65536 + c,
                          acc[mf][nf][0], acc[mf][nf][1]);
                stg_cs_v2(out + (size_t)(r + 8) * 65536 + c,
                          acc[mf][nf][2], acc[mf][nf][3]);
            }
        }
        parity ^= 1;
    }
}

extern "C" void kernel_launch(void* const* d_in, const int* in_sizes, int n_in,
                              void* d_out, int out_size) {
    // metadata order: inputs f32[512,256], indexes i64[512],
    //                 features f32[65536,256], mIoU f32[65536], IoU f32[512];
    //                 output f32[512,65536]
    const float* inputs   = (const float*)d_in[0];
    const float* features = (const float*)d_in[2];
    float* out = (float*)d_out;

    convert_kernel<<<592, 256>>>(features);

    cudaFuncSetAttribute(gemm_kernel,
                         cudaFuncAttributeMaxDynamicSharedMemorySize, SMEM_BYTES);
    // grid.x = m_super (fast): the 4 CTAs sharing each B slab run concurrently
    gemm_kernel<<<dim3(4, GY), BLOCK, SMEM_BYTES>>>(inputs, out);
}